// round 4
// baseline (speedup 1.0000x reference)
#include <cuda_runtime.h>
#include <cuda_bf16.h>
#include <cstdint>

// ---------------------------------------------------------------------------
// MultiHeadRegionalAttention2D
//   x:[1,128,192,192]  wq,wk,wv:[256,128]  out:[1,256,192,192]
//
//   g[head,p]  = (sum_{c in head} q[c,p]*k[c,p]) / 16
//   score_s(p) = softmax over 9 slots of g[head, p+delta_s]   (OOB logit = 0)
//   out[c,p]   = sum_s score_s * v[c, p+delta_s]              (OOB v = 0)
//
// R4 = R3 with the attn grid fixed (36 blocks, not 12):
//  - proj w-operands loaded as ulonglong2 (f32x2 operands = LDS dest regs)
//  - attn packs pixel pairs at stride 96 -> pair-aligned stencil, FFMA2 gather
// ---------------------------------------------------------------------------

#define C_IN   128
#define HDIM   192
#define NPIX   (192*192)          // 36864
#define NHEAD  8
#define HALFW  96

__device__ float d_v [256 * NPIX];        // v projection only
__device__ float d_g [NHEAD * NPIX];
__device__ float d_wT[C_IN * 768];        // [k][m]: m 0..255=wq, 256..511=wk, 512..767=wv

typedef unsigned long long u64;

__device__ __forceinline__ u64 pk2(float a, float b) {
    u64 r; asm("mov.b64 %0,{%1,%2};" : "=l"(r) : "f"(a), "f"(b)); return r;
}
__device__ __forceinline__ u64 fma2(u64 a, u64 b, u64 c) {
    u64 d; asm("fma.rn.f32x2 %0,%1,%2,%3;" : "=l"(d) : "l"(a), "l"(b), "l"(c)); return d;
}
__device__ __forceinline__ float2 up2(u64 a) {
    float2 f; asm("mov.b64 {%0,%1},%2;" : "=f"(f.x), "=f"(f.y) : "l"(a)); return f;
}

// ---------------------------------------------------------------------------
// Kernel 0: transpose weights into d_wT[k][m]
// ---------------------------------------------------------------------------
__global__ __launch_bounds__(256) void wtrans_kernel(
    const float* __restrict__ wq,
    const float* __restrict__ wk,
    const float* __restrict__ wv)
{
    int id = blockIdx.x * 256 + threadIdx.x;        // 0..98303
    int m = id >> 7;
    int k = id & 127;
    float val = (m < 256) ? wq[m * C_IN + k]
              : (m < 512) ? wk[(m - 256) * C_IN + k]
                          : wv[(m - 512) * C_IN + k];
    d_wT[k * 768 + m] = val;
}

// ---------------------------------------------------------------------------
// Kernel 1: fused projection.
//   blockIdx.y <  8 : head mode -> q,k for head y over 128 px -> g (in-block)
//   blockIdx.y >= 8 : v mode -> 64 v-channels -> d_v
// 256 threads: warp w -> 8 channels (mOff=w*8), lane -> 4 pixels.
// ---------------------------------------------------------------------------
__global__ __launch_bounds__(256, 2) void proj_kernel(const float* __restrict__ x)
{
    __shared__ float xs[64 * 128];   // 32 KB  [k][px]   (reused for qk exchange)
    __shared__ float ws[64 * 64];    // 16 KB  [k][c]

    const int y     = blockIdx.y;
    const int pBase = blockIdx.x * 128;
    const int t     = threadIdx.x;
    const int lane  = t & 31;
    const int w     = t >> 5;
    const int pOff  = lane * 4;
    const int mOff  = w * 8;

    const int cFix = t & 63;
    const int kFix = t >> 6;
    const int mcol = (y < 8)
        ? ((cFix < 32) ? y * 32 + cFix : 256 + y * 32 + (cFix - 32))
        : 512 + (y - 8) * 64 + cFix;

    u64 acc[4][4];
    #pragma unroll
    for (int cp = 0; cp < 4; cp++)
        #pragma unroll
        for (int px = 0; px < 4; px++) acc[cp][px] = 0ull;

    for (int kc = 0; kc < 2; kc++) {
        const int k0 = kc * 64;
        {
            const int row0 = t >> 5;
            const int c4   = (t & 31) << 2;
            #pragma unroll
            for (int j = 0; j < 8; j++) {
                int row = row0 + 8 * j;
                *(float4*)(xs + row * 128 + c4) =
                    *(const float4*)(x + (size_t)(k0 + row) * NPIX + pBase + c4);
            }
        }
        #pragma unroll
        for (int j = 0; j < 16; j++) {
            int k = kFix + 4 * j;
            ws[k * 64 + cFix] = d_wT[(size_t)(k0 + k) * 768 + mcol];
        }
        __syncthreads();

        #pragma unroll 4
        for (int k = 0; k < 64; k++) {
            float4 xv = *(const float4*)(xs + k * 128 + pOff);
            u64 xd[4];
            xd[0] = pk2(xv.x, xv.x);
            xd[1] = pk2(xv.y, xv.y);
            xd[2] = pk2(xv.z, xv.z);
            xd[3] = pk2(xv.w, xv.w);
            // weight pairs: f32x2 operands ARE the LDS.128 dest regs (no movs)
            const ulonglong2* wrow = (const ulonglong2*)(ws + k * 64 + mOff);
            ulonglong2 w01 = wrow[0];          // channels (0,1),(2,3)
            ulonglong2 w23 = wrow[1];          // channels (4,5),(6,7)
            u64 wp[4] = { w01.x, w01.y, w23.x, w23.y };
            #pragma unroll
            for (int cp = 0; cp < 4; cp++)
                #pragma unroll
                for (int px = 0; px < 4; px++)
                    acc[cp][px] = fma2(wp[cp], xd[px], acc[cp][px]);
        }
        __syncthreads();
    }

    if (y >= 8) {
        const int cbase = (y - 8) * 64 + mOff;
        #pragma unroll
        for (int cp = 0; cp < 4; cp++) {
            float2 a0 = up2(acc[cp][0]);
            float2 a1 = up2(acc[cp][1]);
            float2 a2 = up2(acc[cp][2]);
            float2 a3 = up2(acc[cp][3]);
            *(float4*)(d_v + (size_t)(cbase + 2 * cp) * NPIX + pBase + pOff) =
                make_float4(a0.x, a1.x, a2.x, a3.x);
            *(float4*)(d_v + (size_t)(cbase + 2 * cp + 1) * NPIX + pBase + pOff) =
                make_float4(a0.y, a1.y, a2.y, a3.y);
        }
    } else {
        float* qsh = xs;               // [32][128]
        float* ps  = xs + 32 * 128;    // [4][128]

        if (w < 4) {
            #pragma unroll
            for (int cp = 0; cp < 4; cp++) {
                float2 a0 = up2(acc[cp][0]);
                float2 a1 = up2(acc[cp][1]);
                float2 a2 = up2(acc[cp][2]);
                float2 a3 = up2(acc[cp][3]);
                int ch = mOff + 2 * cp;
                *(float4*)(qsh + ch * 128 + pOff) =
                    make_float4(a0.x, a1.x, a2.x, a3.x);
                *(float4*)(qsh + (ch + 1) * 128 + pOff) =
                    make_float4(a0.y, a1.y, a2.y, a3.y);
            }
        }
        __syncthreads();
        if (w >= 4) {
            float s0 = 0.f, s1 = 0.f, s2 = 0.f, s3 = 0.f;
            #pragma unroll
            for (int cp = 0; cp < 4; cp++) {
                int ch = (w - 4) * 8 + 2 * cp;
                float4 q0 = *(const float4*)(qsh + ch * 128 + pOff);
                float4 q1 = *(const float4*)(qsh + (ch + 1) * 128 + pOff);
                float2 k0v = up2(acc[cp][0]);
                float2 k1v = up2(acc[cp][1]);
                float2 k2v = up2(acc[cp][2]);
                float2 k3v = up2(acc[cp][3]);
                s0 += k0v.x * q0.x + k0v.y * q1.x;
                s1 += k1v.x * q0.y + k1v.y * q1.y;
                s2 += k2v.x * q0.z + k2v.y * q1.z;
                s3 += k3v.x * q0.w + k3v.y * q1.w;
            }
            *(float4*)(ps + (w - 4) * 128 + pOff) = make_float4(s0, s1, s2, s3);
        }
        __syncthreads();
        if (t < 128) {
            float gv = (ps[t] + ps[128 + t] + ps[256 + t] + ps[384 + t]) * (1.0f / 16.0f);
            d_g[(size_t)y * NPIX + pBase + t] = gv;
        }
    }
}

// ---------------------------------------------------------------------------
// Kernel 2: softmax + weighted gather, pixel pairs packed at stride 96.
// Thread owns 8 px: cols [x,x+4) and [x+96,x+100) of one row -> 4 f32x2 pairs.
// 4608 threads total -> grid.x = 36 at 128 threads/block.
// ---------------------------------------------------------------------------
__global__ __launch_bounds__(128) void attn_kernel(float* __restrict__ out)
{
    const int t   = threadIdx.x;
    const int qid = blockIdx.x * 128 + t;        // 0..4607
    const int hd  = blockIdx.y;
    const int yy0 = qid / 24;                    // row 0..191
    const int x   = (qid - yy0 * 24) * 4;        // 0,4,...,92

    const bool lok  = (x > 0);                   // col x-1 valid
    const bool rgd  = (x < 92);                  // col x+100 valid

    bool rok[3];
    int  roff[3];
    #pragma unroll
    for (int r = 0; r < 3; r++) {
        int yy = yy0 + r - 1;
        rok[r]  = ((unsigned)yy < (unsigned)HDIM);
        roff[r] = yy * HDIM;
    }

    // ---- g windows: left cols x-1..x+4, right cols x+95..x+100 ----
    float wL[3][6], wR[3][6];
    #pragma unroll
    for (int r = 0; r < 3; r++) {
        if (rok[r]) {
            const float* gp = d_g + (size_t)hd * NPIX + roff[r];
            wL[r][0] = lok ? gp[x - 1] : 0.f;
            float4 a = *(const float4*)(gp + x);
            wL[r][1] = a.x; wL[r][2] = a.y; wL[r][3] = a.z; wL[r][4] = a.w;
            wL[r][5] = gp[x + 4];
            wR[r][0] = gp[x + 95];
            float4 b = *(const float4*)(gp + x + 96);
            wR[r][1] = b.x; wR[r][2] = b.y; wR[r][3] = b.z; wR[r][4] = b.w;
            wR[r][5] = rgd ? gp[x + 100] : 0.f;
        } else {
            #pragma unroll
            for (int i = 0; i < 6; i++) { wL[r][i] = 0.f; wR[r][i] = 0.f; }
        }
    }

    // ---- softmax per pixel, then pack (left,right) weight pairs ----
    u64 wt2[9][4];
    #pragma unroll
    for (int i = 0; i < 4; i++) {
        float eL[9], eR[9];
        float mL = -1e30f, mR = -1e30f;
        #pragma unroll
        for (int r = 0; r < 3; r++)
            #pragma unroll
            for (int j = 0; j < 3; j++) {
                mL = fmaxf(mL, wL[r][i + j]);
                mR = fmaxf(mR, wR[r][i + j]);
            }
        float zL = 0.f, zR = 0.f;
        #pragma unroll
        for (int r = 0; r < 3; r++)
            #pragma unroll
            for (int j = 0; j < 3; j++) {
                int s = r * 3 + j;
                float a = __expf(wL[r][i + j] - mL);
                float b = __expf(wR[r][i + j] - mR);
                eL[s] = a; eR[s] = b;
                zL += a; zR += b;
            }
        float iL = __fdividef(1.f, zL);
        float iR = __fdividef(1.f, zR);
        #pragma unroll
        for (int s = 0; s < 9; s++)
            wt2[s][i] = pk2(eL[s] * iL, eR[s] * iR);
    }

    // ---- gather over 32 channels ----
    const float* vbase = d_v + (size_t)(hd * 32) * NPIX;
    float* obase       = out + (size_t)(hd * 32) * NPIX;
    const int pL = yy0 * HDIM + x;
    const int pR = pL + HALFW;

    for (int c = 0; c < 32; c++) {
        const float* vr = vbase + (size_t)c * NPIX;
        u64 acc[4] = {0ull, 0ull, 0ull, 0ull};
        #pragma unroll
        for (int r = 0; r < 3; r++) {
            u64 vp[6];
            if (rok[r]) {
                const float* p = vr + roff[r];
                float l0 = lok ? p[x - 1] : 0.f;
                float4 a = *(const float4*)(p + x);
                float l5 = p[x + 4];
                float r0 = p[x + 95];
                float4 b = *(const float4*)(p + x + 96);
                float r5 = rgd ? p[x + 100] : 0.f;
                vp[0] = pk2(l0,  r0);
                vp[1] = pk2(a.x, b.x);
                vp[2] = pk2(a.y, b.y);
                vp[3] = pk2(a.z, b.z);
                vp[4] = pk2(a.w, b.w);
                vp[5] = pk2(l5,  r5);
            } else {
                #pragma unroll
                for (int i = 0; i < 6; i++) vp[i] = 0ull;
            }
            #pragma unroll
            for (int j = 0; j < 3; j++)
                #pragma unroll
                for (int i = 0; i < 4; i++)
                    acc[i] = fma2(wt2[r * 3 + j][i], vp[i + j], acc[i]);
        }
        float2 a0 = up2(acc[0]);
        float2 a1 = up2(acc[1]);
        float2 a2 = up2(acc[2]);
        float2 a3 = up2(acc[3]);
        float* op = obase + (size_t)c * NPIX;
        *(float4*)(op + pL) = make_float4(a0.x, a1.x, a2.x, a3.x);
        *(float4*)(op + pR) = make_float4(a0.y, a1.y, a2.y, a3.y);
    }
}

// ---------------------------------------------------------------------------
extern "C" void kernel_launch(void* const* d_in, const int* in_sizes, int n_in,
                              void* d_out, int out_size)
{
    const float* x  = (const float*)d_in[0];
    const float* wq = (const float*)d_in[1];
    const float* wk = (const float*)d_in[2];
    const float* wv = (const float*)d_in[3];
    float* out = (float*)d_out;

    wtrans_kernel<<<768 * C_IN / 256, 256>>>(wq, wk, wv);
    proj_kernel<<<dim3(NPIX / 128, 12), 256>>>(x);
    attn_kernel<<<dim3((NPIX / 8) / 128, NHEAD), 128>>>(out);   // (36, 8)
}

// round 8
// speedup vs baseline: 1.7437x; 1.7437x over previous
#include <cuda_runtime.h>
#include <cuda_bf16.h>
#include <cstdint>

// ---------------------------------------------------------------------------
// MultiHeadRegionalAttention2D
//   x:[1,128,192,192]  wq,wk,wv:[256,128]  out:[1,256,192,192]
//
//   g[head,p]  = (sum_{c in head} q[c,p]*k[c,p]) / 16
//   score_s(p) = softmax over 9 slots of g[head, p+delta_s]   (OOB logit = 0)
//   out[c,p]   = sum_s score_s * v[c, p+delta_s]              (OOB v = 0)
//
// R8 = R7 resubmit (infra failed before it ran):
//   proven R2 proj/wtrans + attn parallelized 4x over channel groups
//   (attn was latency-bound at ~8 warps/SM; now ~30+ warps/SM).
// ---------------------------------------------------------------------------

#define C_IN   128
#define HDIM   192
#define NPIX   (192*192)          // 36864
#define NHEAD  8

__device__ float d_v [256 * NPIX];        // v projection only
__device__ float d_g [NHEAD * NPIX];
__device__ float d_wT[C_IN * 768];        // [k][m]: m 0..255=wq, 256..511=wk, 512..767=wv

typedef unsigned long long u64;

__device__ __forceinline__ u64 pk2(float a, float b) {
    u64 r; asm("mov.b64 %0,{%1,%2};" : "=l"(r) : "f"(a), "f"(b)); return r;
}
__device__ __forceinline__ u64 fma2(u64 a, u64 b, u64 c) {
    u64 d; asm("fma.rn.f32x2 %0,%1,%2,%3;" : "=l"(d) : "l"(a), "l"(b), "l"(c)); return d;
}
__device__ __forceinline__ float2 up2(u64 a) {
    float2 f; asm("mov.b64 {%0,%1},%2;" : "=f"(f.x), "=f"(f.y) : "l"(a)); return f;
}

// ---------------------------------------------------------------------------
// Kernel 0: transpose weights into d_wT[k][m]
// ---------------------------------------------------------------------------
__global__ __launch_bounds__(256) void wtrans_kernel(
    const float* __restrict__ wq,
    const float* __restrict__ wk,
    const float* __restrict__ wv)
{
    int id = blockIdx.x * 256 + threadIdx.x;        // 0..98303
    int m = id >> 7;
    int k = id & 127;
    float val = (m < 256) ? wq[m * C_IN + k]
              : (m < 512) ? wk[(m - 256) * C_IN + k]
                          : wv[(m - 512) * C_IN + k];
    d_wT[k * 768 + m] = val;
}

// ---------------------------------------------------------------------------
// Kernel 1: fused projection (identical to the proven 181us version).
//   blockIdx.y <  8 : head mode -> q,k for head y over 128 px -> g (in-block)
//   blockIdx.y >= 8 : v mode -> 64 v-channels -> d_v
// ---------------------------------------------------------------------------
__global__ __launch_bounds__(256, 2) void proj_kernel(const float* __restrict__ x)
{
    __shared__ float xs[64 * 128];   // 32 KB  [k][px]   (reused for qk exchange)
    __shared__ float ws[64 * 64];    // 16 KB  [k][c]

    const int y     = blockIdx.y;
    const int pBase = blockIdx.x * 128;
    const int t     = threadIdx.x;
    const int lane  = t & 31;
    const int w     = t >> 5;
    const int pOff  = lane * 4;
    const int mOff  = w * 8;

    const int cFix = t & 63;
    const int kFix = t >> 6;
    const int mcol = (y < 8)
        ? ((cFix < 32) ? y * 32 + cFix : 256 + y * 32 + (cFix - 32))
        : 512 + (y - 8) * 64 + cFix;

    u64 acc[4][4];
    #pragma unroll
    for (int cp = 0; cp < 4; cp++)
        #pragma unroll
        for (int px = 0; px < 4; px++) acc[cp][px] = 0ull;

    for (int kc = 0; kc < 2; kc++) {
        const int k0 = kc * 64;
        {
            const int row0 = t >> 5;
            const int c4   = (t & 31) << 2;
            #pragma unroll
            for (int j = 0; j < 8; j++) {
                int row = row0 + 8 * j;
                *(float4*)(xs + row * 128 + c4) =
                    *(const float4*)(x + (size_t)(k0 + row) * NPIX + pBase + c4);
            }
        }
        #pragma unroll
        for (int j = 0; j < 16; j++) {
            int k = kFix + 4 * j;
            ws[k * 64 + cFix] = d_wT[(size_t)(k0 + k) * 768 + mcol];
        }
        __syncthreads();

        #pragma unroll 4
        for (int k = 0; k < 64; k++) {
            float4 xv = *(const float4*)(xs + k * 128 + pOff);
            u64 xd[4];
            xd[0] = pk2(xv.x, xv.x);
            xd[1] = pk2(xv.y, xv.y);
            xd[2] = pk2(xv.z, xv.z);
            xd[3] = pk2(xv.w, xv.w);
            float4 wa = *(const float4*)(ws + k * 64 + mOff);
            float4 wb = *(const float4*)(ws + k * 64 + mOff + 4);
            u64 wp[4];
            wp[0] = pk2(wa.x, wa.y);
            wp[1] = pk2(wa.z, wa.w);
            wp[2] = pk2(wb.x, wb.y);
            wp[3] = pk2(wb.z, wb.w);
            #pragma unroll
            for (int cp = 0; cp < 4; cp++)
                #pragma unroll
                for (int px = 0; px < 4; px++)
                    acc[cp][px] = fma2(wp[cp], xd[px], acc[cp][px]);
        }
        __syncthreads();
    }

    if (y >= 8) {
        const int cbase = (y - 8) * 64 + mOff;
        #pragma unroll
        for (int cp = 0; cp < 4; cp++) {
            float2 a0 = up2(acc[cp][0]);
            float2 a1 = up2(acc[cp][1]);
            float2 a2 = up2(acc[cp][2]);
            float2 a3 = up2(acc[cp][3]);
            *(float4*)(d_v + (size_t)(cbase + 2 * cp) * NPIX + pBase + pOff) =
                make_float4(a0.x, a1.x, a2.x, a3.x);
            *(float4*)(d_v + (size_t)(cbase + 2 * cp + 1) * NPIX + pBase + pOff) =
                make_float4(a0.y, a1.y, a2.y, a3.y);
        }
    } else {
        float* qsh = xs;               // [32][128]
        float* ps  = xs + 32 * 128;    // [4][128]

        if (w < 4) {
            #pragma unroll
            for (int cp = 0; cp < 4; cp++) {
                float2 a0 = up2(acc[cp][0]);
                float2 a1 = up2(acc[cp][1]);
                float2 a2 = up2(acc[cp][2]);
                float2 a3 = up2(acc[cp][3]);
                int ch = mOff + 2 * cp;
                *(float4*)(qsh + ch * 128 + pOff) =
                    make_float4(a0.x, a1.x, a2.x, a3.x);
                *(float4*)(qsh + (ch + 1) * 128 + pOff) =
                    make_float4(a0.y, a1.y, a2.y, a3.y);
            }
        }
        __syncthreads();
        if (w >= 4) {
            float s0 = 0.f, s1 = 0.f, s2 = 0.f, s3 = 0.f;
            #pragma unroll
            for (int cp = 0; cp < 4; cp++) {
                int ch = (w - 4) * 8 + 2 * cp;
                float4 q0 = *(const float4*)(qsh + ch * 128 + pOff);
                float4 q1 = *(const float4*)(qsh + (ch + 1) * 128 + pOff);
                float2 k0v = up2(acc[cp][0]);
                float2 k1v = up2(acc[cp][1]);
                float2 k2v = up2(acc[cp][2]);
                float2 k3v = up2(acc[cp][3]);
                s0 += k0v.x * q0.x + k0v.y * q1.x;
                s1 += k1v.x * q0.y + k1v.y * q1.y;
                s2 += k2v.x * q0.z + k2v.y * q1.z;
                s3 += k3v.x * q0.w + k3v.y * q1.w;
            }
            *(float4*)(ps + (w - 4) * 128 + pOff) = make_float4(s0, s1, s2, s3);
        }
        __syncthreads();
        if (t < 128) {
            float gv = (ps[t] + ps[128 + t] + ps[256 + t] + ps[384 + t]) * (1.0f / 16.0f);
            d_g[(size_t)y * NPIX + pBase + t] = gv;
        }
    }
}

// ---------------------------------------------------------------------------
// Kernel 2: softmax over 9 region slots + weighted gather of v.
// 256 threads = 64 pixel-quads x 4 channel-groups (8 channels each).
// Softmax recomputed per channel-group (cheap, g is L2-resident);
// 4x more warps in flight hides the dependent-LDG channel loop.
// ---------------------------------------------------------------------------
__global__ __launch_bounds__(256) void attn_kernel(float* __restrict__ out)
{
    const int t    = threadIdx.x;
    const int cg   = t >> 6;                         // channel group 0..3
    const int quad = blockIdx.x * 64 + (t & 63);     // 0..9215
    const int hd   = blockIdx.y;
    const int p4   = quad * 4;
    const int yy0  = p4 / HDIM;
    const int x4   = p4 - yy0 * HDIM;

    bool rok[3];
    int  roff[3];
    const bool lok  = (x4 > 0);
    const bool rokc = (x4 + 4 < HDIM);

    float win[3][6];
    #pragma unroll
    for (int r = 0; r < 3; r++) {
        int yy = yy0 + r - 1;
        rok[r]  = ((unsigned)yy < (unsigned)HDIM);
        roff[r] = yy * HDIM + x4;
        if (rok[r]) {
            const float* gp = d_g + (size_t)hd * NPIX + roff[r];
            win[r][0] = lok ? gp[-1] : 0.f;
            float4 m4 = *(const float4*)gp;
            win[r][1] = m4.x; win[r][2] = m4.y; win[r][3] = m4.z; win[r][4] = m4.w;
            win[r][5] = rokc ? gp[4] : 0.f;
        } else {
            #pragma unroll
            for (int i = 0; i < 6; i++) win[r][i] = 0.f;
        }
    }

    float wt[9][4];
    #pragma unroll
    for (int px = 0; px < 4; px++) {
        float l[9];
        float m = -1e30f;
        #pragma unroll
        for (int r = 0; r < 3; r++)
            #pragma unroll
            for (int j = 0; j < 3; j++) {
                float v = win[r][px + j];
                l[r * 3 + j] = v;
                m = fmaxf(m, v);
            }
        float z = 0.f;
        #pragma unroll
        for (int s = 0; s < 9; s++) {
            float e = __expf(l[s] - m);
            wt[s][px] = e;
            z += e;
        }
        float inv = __fdividef(1.f, z);
        #pragma unroll
        for (int s = 0; s < 9; s++) wt[s][px] *= inv;
    }

    const float* vbase = d_v + (size_t)(hd * 32 + cg * 8) * NPIX;
    float* obase       = out + (size_t)(hd * 32 + cg * 8) * NPIX;

    #pragma unroll
    for (int c = 0; c < 8; c++) {
        const float* vr = vbase + (size_t)c * NPIX;
        float a0 = 0.f, a1 = 0.f, a2 = 0.f, a3 = 0.f;
        #pragma unroll
        for (int r = 0; r < 3; r++) {
            float vw[6];
            if (rok[r]) {
                const float* vp = vr + roff[r];
                vw[0] = lok ? vp[-1] : 0.f;
                float4 m4 = *(const float4*)vp;
                vw[1] = m4.x; vw[2] = m4.y; vw[3] = m4.z; vw[4] = m4.w;
                vw[5] = rokc ? vp[4] : 0.f;
            } else {
                #pragma unroll
                for (int i = 0; i < 6; i++) vw[i] = 0.f;
            }
            #pragma unroll
            for (int j = 0; j < 3; j++) {
                const int s = r * 3 + j;
                a0 += wt[s][0] * vw[0 + j];
                a1 += wt[s][1] * vw[1 + j];
                a2 += wt[s][2] * vw[2 + j];
                a3 += wt[s][3] * vw[3 + j];
            }
        }
        *(float4*)(obase + (size_t)c * NPIX + p4) = make_float4(a0, a1, a2, a3);
    }
}

// ---------------------------------------------------------------------------
extern "C" void kernel_launch(void* const* d_in, const int* in_sizes, int n_in,
                              void* d_out, int out_size)
{
    const float* x  = (const float*)d_in[0];
    const float* wq = (const float*)d_in[1];
    const float* wk = (const float*)d_in[2];
    const float* wv = (const float*)d_in[3];
    float* out = (float*)d_out;

    wtrans_kernel<<<768 * C_IN / 256, 256>>>(wq, wk, wv);
    proj_kernel<<<dim3(NPIX / 128, 12), 256>>>(x);
    // 64 quads x 4 channel-groups per block: grid (9216/64, 8)
    attn_kernel<<<dim3(NPIX / 4 / 64, NHEAD), 256>>>(out);
}

// round 9
// speedup vs baseline: 1.8920x; 1.0850x over previous
#include <cuda_runtime.h>
#include <cuda_bf16.h>
#include <cstdint>

// ---------------------------------------------------------------------------
// MultiHeadRegionalAttention2D — R9: HMMA (mma.sync bf16) projection
//   x:[1,128,192,192]  wq,wk,wv:[256,128]  out:[1,256,192,192]
//
//   qkv = W x  via 3-term bf16 split: whi*xhi + wlo*xhi + whi*xlo  (fp32 acc)
//   g[head,p]  = (sum_{c in head} q[c,p]*k[c,p]) / 16
//   score_s(p) = softmax over 9 slots of g[head, p+delta_s]  (OOB logit = 0)
//   out[c,p]   = sum_s score_s * v[c, p+delta_s]             (OOB v = 0)
// ---------------------------------------------------------------------------

#define C_IN   128
#define HDIM   192
#define NPIX   (192*192)          // 36864
#define NHEAD  8
#define SPAD   72                 // smem row stride in bf16 (conflict-free ldmatrix)

__device__ float          d_qkv[768 * NPIX];          // 0..255 q, 256..511 k, 512..767 v
__device__ float          d_g  [NHEAD * NPIX];
__device__ __nv_bfloat16  d_whi[768 * 128];           // [m][k]
__device__ __nv_bfloat16  d_wlo[768 * 128];
__device__ __nv_bfloat16  d_xhi[(size_t)NPIX * 128];  // [px][k]
__device__ __nv_bfloat16  d_xlo[(size_t)NPIX * 128];

typedef unsigned int u32;

__device__ __forceinline__ u32 s2u(const void* p) {
    return (u32)__cvta_generic_to_shared(p);
}
__device__ __forceinline__ void ldm4(u32* r, u32 addr) {
    asm volatile("ldmatrix.sync.aligned.m8n8.x4.shared.b16 {%0,%1,%2,%3}, [%4];"
                 : "=r"(r[0]), "=r"(r[1]), "=r"(r[2]), "=r"(r[3]) : "r"(addr));
}
__device__ __forceinline__ void mma16816(float* c, const u32* a, const u32* b) {
    asm volatile(
        "mma.sync.aligned.m16n8k16.row.col.f32.bf16.bf16.f32 "
        "{%0,%1,%2,%3}, {%4,%5,%6,%7}, {%8,%9}, {%0,%1,%2,%3};"
        : "+f"(c[0]), "+f"(c[1]), "+f"(c[2]), "+f"(c[3])
        : "r"(a[0]), "r"(a[1]), "r"(a[2]), "r"(a[3]), "r"(b[0]), "r"(b[1]));
}

// ---------------------------------------------------------------------------
// Kernel A: split weights -> bf16 hi/lo, row-major [m][k]
// ---------------------------------------------------------------------------
__global__ __launch_bounds__(256) void wsplit_kernel(
    const float* __restrict__ wq, const float* __restrict__ wk,
    const float* __restrict__ wv)
{
    int id = blockIdx.x * 256 + threadIdx.x;   // 0..98303 = m*128+k
    int m = id >> 7;
    int k = id & 127;
    float v = (m < 256) ? wq[m * C_IN + k]
            : (m < 512) ? wk[(m - 256) * C_IN + k]
                        : wv[(m - 512) * C_IN + k];
    __nv_bfloat16 h = __float2bfloat16(v);
    d_whi[id] = h;
    d_wlo[id] = __float2bfloat16(v - __bfloat162float(h));
}

// ---------------------------------------------------------------------------
// Kernel B: transpose + split x -> d_xhi/d_xlo [px][128] bf16
// ---------------------------------------------------------------------------
__global__ __launch_bounds__(256) void xsplit_kernel(const float* __restrict__ x)
{
    __shared__ float ts[128][33];
    const int pxBase = blockIdx.x * 32;
    const int t = threadIdx.x;
    #pragma unroll
    for (int i = 0; i < 16; i++) {
        int idx = t + i * 256;             // 0..4095
        int k  = idx >> 5;
        int px = idx & 31;
        ts[k][px] = x[(size_t)k * NPIX + pxBase + px];
    }
    __syncthreads();
    const int px = t >> 3;                 // 0..31
    const int c  = (t & 7) * 16;           // k start
    __nv_bfloat16 hi[16], lo[16];
    #pragma unroll
    for (int j = 0; j < 16; j++) {
        float v = ts[c + j][px];
        __nv_bfloat16 h = __float2bfloat16(v);
        hi[j] = h;
        lo[j] = __float2bfloat16(v - __bfloat162float(h));
    }
    size_t base = (size_t)(pxBase + px) * 128 + c;
    *(uint4*)(d_xhi + base)     = ((const uint4*)hi)[0];
    *(uint4*)(d_xhi + base + 8) = ((const uint4*)hi)[1];
    *(uint4*)(d_xlo + base)     = ((const uint4*)lo)[0];
    *(uint4*)(d_xlo + base + 8) = ((const uint4*)lo)[1];
}

// ---------------------------------------------------------------------------
// Kernel C: HMMA GEMM.  D[m][px] = sum_k w[m][k] x[k][px], 3 bf16 split terms.
// CTA: M=128 x N=128px, 8 warps, warp tile 32m x 64px.
// K as 6 chunks of 64 (3 terms x 2); smem tiles 128 x 64 bf16, stride SPAD=72.
// A,B fragments via non-trans ldmatrix from k-contiguous layouts (row.col mma).
// ---------------------------------------------------------------------------
__global__ __launch_bounds__(256) void mma_proj_kernel()
{
    __shared__ __nv_bfloat16 smA[128 * SPAD];   // 18 KB
    __shared__ __nv_bfloat16 smB[128 * SPAD];   // 18 KB

    const int t    = threadIdx.x;
    const int lane = t & 31;
    const int w    = t >> 5;
    const int wm   = w >> 1;          // 0..3  (32-row m slice)
    const int wn   = w & 1;           // 0..1  (64-px slice)
    const int pxBase = blockIdx.x * 128;
    const int mBase  = blockIdx.y * 128;

    float acc[2][8][4] = {};          // [mf][nf][c]

    // piece tables: term sources + k offset
    const int pA[6] = {0, 1, 0, 1, 0, 0};    // 0=hi 1=lo (weights)
    const int pB[6] = {0, 0, 0, 0, 1, 1};    // 0=hi 1=lo (x)
    const int pK[6] = {0, 0, 64, 64, 0, 64};

    const int rowL = t >> 3;          // 0..31 base row for loads (x8 = 256 thr)
    const int c8   = t & 7;           // 16-byte column within 64-k row

    for (int piece = 0; piece < 6; piece++) {
        if (piece > 0) __syncthreads();     // previous mma frags consumed
        const __nv_bfloat16* As = (pA[piece] ? d_wlo : d_whi);
        const __nv_bfloat16* Bs = (pB[piece] ? d_xlo : d_xhi);
        const int kOff = pK[piece];
        #pragma unroll
        for (int i = 0; i < 4; i++) {
            int row = rowL + i * 32;
            *(uint4*)(smA + row * SPAD + c8 * 8) =
                *((const uint4*)(As + (size_t)(mBase + row) * 128 + kOff) + c8);
            *(uint4*)(smB + row * SPAD + c8 * 8) =
                *((const uint4*)(Bs + (size_t)(pxBase + row) * 128 + kOff) + c8);
        }
        __syncthreads();

        const int lr = lane & 15;
        const int lh = (lane >> 4) * 8;
        #pragma unroll
        for (int kk = 0; kk < 4; kk++) {
            u32 a[2][4];
            #pragma unroll
            for (int mf = 0; mf < 2; mf++)
                ldm4(a[mf], s2u(smA + (wm * 32 + mf * 16 + lr) * SPAD + kk * 16 + lh));
            u32 b[8][2];
            #pragma unroll
            for (int nf2 = 0; nf2 < 4; nf2++) {
                u32 r[4];
                ldm4(r, s2u(smB + (wn * 64 + nf2 * 16 + lr) * SPAD + kk * 16 + lh));
                b[nf2 * 2][0]     = r[0];
                b[nf2 * 2][1]     = r[2];
                b[nf2 * 2 + 1][0] = r[1];
                b[nf2 * 2 + 1][1] = r[3];
            }
            #pragma unroll
            for (int mf = 0; mf < 2; mf++)
                #pragma unroll
                for (int nf = 0; nf < 8; nf++)
                    mma16816(acc[mf][nf], a[mf], b[nf]);
        }
    }

    // epilogue: C frag (m16n8): c0,c1 -> (row, col..+1); c2,c3 -> (row+8, ...)
    const int rQ = lane >> 2;
    const int cQ = (lane & 3) * 2;
    #pragma unroll
    for (int mf = 0; mf < 2; mf++) {
        #pragma unroll
        for (int nf = 0; nf < 8; nf++) {
            int row = mBase + wm * 32 + mf * 16 + rQ;
            int col = pxBase + wn * 64 + nf * 8 + cQ;
            *(float2*)(d_qkv + (size_t)row * NPIX + col) =
                make_float2(acc[mf][nf][0], acc[mf][nf][1]);
            *(float2*)(d_qkv + (size_t)(row + 8) * NPIX + col) =
                make_float2(acc[mf][nf][2], acc[mf][nf][3]);
        }
    }
}

// ---------------------------------------------------------------------------
// Kernel D: g[head][p] = (1/16) * sum_{c in head} q[c,p]*k[c,p]
// ---------------------------------------------------------------------------
__global__ __launch_bounds__(256) void g_kernel()
{
    const int p  = (blockIdx.x * blockDim.x + threadIdx.x) * 4;
    const int hd = blockIdx.y;

    const float* qp = d_qkv + (size_t)(hd * 32) * NPIX + p;
    const float* kp = d_qkv + (size_t)(256 + hd * 32) * NPIX + p;

    float a0 = 0.f, a1 = 0.f, a2 = 0.f, a3 = 0.f;
    #pragma unroll 8
    for (int c = 0; c < 32; c++) {
        float4 q = *(const float4*)(qp + (size_t)c * NPIX);
        float4 k = *(const float4*)(kp + (size_t)c * NPIX);
        a0 += q.x * k.x;
        a1 += q.y * k.y;
        a2 += q.z * k.z;
        a3 += q.w * k.w;
    }
    const float s = 1.0f / 16.0f;
    *(float4*)(d_g + (size_t)hd * NPIX + p) = make_float4(a0 * s, a1 * s, a2 * s, a3 * s);
}

// ---------------------------------------------------------------------------
// Kernel E: softmax + weighted gather (R8 proven; v lives at d_qkv rows 512+).
// 256 threads = 64 pixel-quads x 4 channel-groups (8 channels each).
// ---------------------------------------------------------------------------
__global__ __launch_bounds__(256) void attn_kernel(float* __restrict__ out)
{
    const int t    = threadIdx.x;
    const int cg   = t >> 6;
    const int quad = blockIdx.x * 64 + (t & 63);
    const int hd   = blockIdx.y;
    const int p4   = quad * 4;
    const int yy0  = p4 / HDIM;
    const int x4   = p4 - yy0 * HDIM;

    bool rok[3];
    int  roff[3];
    const bool lok  = (x4 > 0);
    const bool rokc = (x4 + 4 < HDIM);

    float win[3][6];
    #pragma unroll
    for (int r = 0; r < 3; r++) {
        int yy = yy0 + r - 1;
        rok[r]  = ((unsigned)yy < (unsigned)HDIM);
        roff[r] = yy * HDIM + x4;
        if (rok[r]) {
            const float* gp = d_g + (size_t)hd * NPIX + roff[r];
            win[r][0] = lok ? gp[-1] : 0.f;
            float4 m4 = *(const float4*)gp;
            win[r][1] = m4.x; win[r][2] = m4.y; win[r][3] = m4.z; win[r][4] = m4.w;
            win[r][5] = rokc ? gp[4] : 0.f;
        } else {
            #pragma unroll
            for (int i = 0; i < 6; i++) win[r][i] = 0.f;
        }
    }

    float wt[9][4];
    #pragma unroll
    for (int px = 0; px < 4; px++) {
        float l[9];
        float m = -1e30f;
        #pragma unroll
        for (int r = 0; r < 3; r++)
            #pragma unroll
            for (int j = 0; j < 3; j++) {
                float v = win[r][px + j];
                l[r * 3 + j] = v;
                m = fmaxf(m, v);
            }
        float z = 0.f;
        #pragma unroll
        for (int s = 0; s < 9; s++) {
            float e = __expf(l[s] - m);
            wt[s][px] = e;
            z += e;
        }
        float inv = __fdividef(1.f, z);
        #pragma unroll
        for (int s = 0; s < 9; s++) wt[s][px] *= inv;
    }

    const float* vbase = d_qkv + (size_t)(512 + hd * 32 + cg * 8) * NPIX;
    float* obase       = out   + (size_t)(hd * 32 + cg * 8) * NPIX;

    #pragma unroll
    for (int c = 0; c < 8; c++) {
        const float* vr = vbase + (size_t)c * NPIX;
        float a0 = 0.f, a1 = 0.f, a2 = 0.f, a3 = 0.f;
        #pragma unroll
        for (int r = 0; r < 3; r++) {
            float vw[6];
            if (rok[r]) {
                const float* vp = vr + roff[r];
                vw[0] = lok ? vp[-1] : 0.f;
                float4 m4 = *(const float4*)vp;
                vw[1] = m4.x; vw[2] = m4.y; vw[3] = m4.z; vw[4] = m4.w;
                vw[5] = rokc ? vp[4] : 0.f;
            } else {
                #pragma unroll
                for (int i = 0; i < 6; i++) vw[i] = 0.f;
            }
            #pragma unroll
            for (int j = 0; j < 3; j++) {
                const int s = r * 3 + j;
                a0 += wt[s][0] * vw[0 + j];
                a1 += wt[s][1] * vw[1 + j];
                a2 += wt[s][2] * vw[2 + j];
                a3 += wt[s][3] * vw[3 + j];
            }
        }
        *(float4*)(obase + (size_t)c * NPIX + p4) = make_float4(a0, a1, a2, a3);
    }
}

// ---------------------------------------------------------------------------
extern "C" void kernel_launch(void* const* d_in, const int* in_sizes, int n_in,
                              void* d_out, int out_size)
{
    const float* x  = (const float*)d_in[0];
    const float* wq = (const float*)d_in[1];
    const float* wk = (const float*)d_in[2];
    const float* wv = (const float*)d_in[3];
    float* out = (float*)d_out;

    wsplit_kernel<<<768 * C_IN / 256, 256>>>(wq, wk, wv);
    xsplit_kernel<<<NPIX / 32, 256>>>(x);
    mma_proj_kernel<<<dim3(NPIX / 128, 768 / 128), 256>>>();
    g_kernel<<<dim3(NPIX / (256 * 4), NHEAD), 256>>>();
    attn_kernel<<<dim3(NPIX / 4 / 64, NHEAD), 256>>>(out);
}